// round 6
// baseline (speedup 1.0000x reference)
#include <cuda_runtime.h>
#include <math.h>
#include <float.h>

// ---------------- scratch (device globals; zero-initialized at load) -------
#define MAXC   128
#define MAXC2  256
#define MAXN   65536
#define MAXD   768
#define RSPLIT 8
#define SC_BLOCKS 64

__device__ int      g_counts[MAXC];
__device__ int      g_offsets[MAXC + 1];
__device__ int      g_bh[SC_BLOCKS][MAXC];     // per-block class histogram
__device__ int      g_bbase[SC_BLOCKS][MAXC];  // per-block class base offset
__device__ int      g_perm[MAXN];
__device__ float    g_part[RSPLIT * 100 * 2 * MAXD];   // [r][class][matrix][col]
__device__ float    g_znorm[MAXC2 * MAXD];             // row-major
__device__ float    g_znormT[MAXD * MAXC2];            // [k][j], cols >=C2 stay 0
__device__ float    g_rowloss[MAXC2];
__device__ unsigned g_ctr1;   // hist completion
__device__ unsigned g_ctr2;   // loss completion

// ---------------- hist + prefix + per-block bases (fused) ------------------

#define H_TPB 256
__global__ void __launch_bounds__(H_TPB)
k_hist(const int* __restrict__ labels, int N, const int* __restrict__ task_id) {
    __shared__ int sh[MAXC];
    __shared__ bool last;
    int end_i = (*task_id + 1) * 10;
    int per = (N + SC_BLOCKS - 1) / SC_BLOCKS;
    int b0 = blockIdx.x * per;
    int b1 = min(N, b0 + per);

    for (int t = threadIdx.x; t < MAXC; t += H_TPB) sh[t] = 0;
    __syncthreads();
    for (int i = b0 + threadIdx.x; i < b1; i += H_TPB) {
        int lab = labels[i];
        if (lab >= 0 && lab < end_i) atomicAdd(&sh[lab], 1);
    }
    __syncthreads();
    for (int t = threadIdx.x; t < MAXC; t += H_TPB) {
        g_bh[blockIdx.x][t] = sh[t];
        if (t < end_i && sh[t]) atomicAdd(&g_counts[t], sh[t]);
    }
    __threadfence();
    if (threadIdx.x == 0)
        last = (atomicAdd(&g_ctr1, 1u) == gridDim.x - 1);
    __syncthreads();
    if (last) {
        __threadfence();
        if (threadIdx.x == 0) {
            int acc = 0;
            for (int c = 0; c < end_i; c++) {
                g_offsets[c] = acc;
                acc += g_counts[c];
            }
            g_offsets[end_i] = acc;
            g_ctr1 = 0;
        }
        __syncthreads();
        int c = threadIdx.x;
        if (c < end_i) {
            int acc = g_offsets[c];
#pragma unroll 8
            for (int b = 0; b < SC_BLOCKS; b++) {
                g_bbase[b][c] = acc;
                acc += g_bh[b][c];
            }
        }
    }
}

// ---------------- scatter: deterministic block bases, smem cursors ---------

#define SC_TPB 256
__global__ void __launch_bounds__(SC_TPB)
k_scatter(const int* __restrict__ labels, int N, const int* __restrict__ task_id) {
    __shared__ int lcur[MAXC];
    __shared__ int lbase[MAXC];
    int end_i = (*task_id + 1) * 10;
    int per = (N + SC_BLOCKS - 1) / SC_BLOCKS;
    int b0 = blockIdx.x * per;
    int b1 = min(N, b0 + per);

    for (int t = threadIdx.x; t < MAXC; t += SC_TPB) {
        lcur[t]  = 0;
        lbase[t] = g_bbase[blockIdx.x][t];
    }
    __syncthreads();
    for (int i = b0 + threadIdx.x; i < b1; i += SC_TPB) {
        int lab = labels[i];
        if (lab >= 0 && lab < end_i) {
            int pos = lbase[lab] + atomicAdd(&lcur[lab], 1);
            g_perm[pos] = i;
        }
    }
}

// ---------------- segment-sum (HBM-bound) ----------------------------------
// grid (100 classes, RSPLIT row-splits, 2 matrices), 192 thr, float4/thread.
// perm is coarsely ascending per class -> localized DRAM streams.

#define SEG_TPB 192
#define CHUNK   64

__global__ void __launch_bounds__(SEG_TPB)
k_segsum(const float* __restrict__ z1, const float* __restrict__ z2,
         const int* __restrict__ task_id) {
    __shared__ int sp[CHUNK];
    int end_i = (*task_id + 1) * 10;
    int c = blockIdx.x;
    int r = blockIdx.y;
    int m = blockIdx.z;
    if (c >= end_i) return;

    int start = g_offsets[c], endo = g_offsets[c + 1];
    int len = endo - start;
    int s0 = start + (int)(((long long)len * r) / RSPLIT);
    int s1 = start + (int)(((long long)len * (r + 1)) / RSPLIT);

    const float4* __restrict__ zv = (const float4*)(m ? z2 : z1);
    const int tid = threadIdx.x;
    const int strideV = MAXD / 4;   // 192

    float4 a = make_float4(0.f, 0.f, 0.f, 0.f);

    for (int base = s0; base < s1; base += CHUNK) {
        int n = min(CHUNK, s1 - base);
        __syncthreads();
        for (int t = tid; t < n; t += SEG_TPB) sp[t] = g_perm[base + t];
        __syncthreads();
        int k = 0;
        for (; k + 8 <= n; k += 8) {
            float4 v0 = __ldcs(&zv[(size_t)sp[k]     * strideV + tid]);
            float4 v1 = __ldcs(&zv[(size_t)sp[k + 1] * strideV + tid]);
            float4 v2 = __ldcs(&zv[(size_t)sp[k + 2] * strideV + tid]);
            float4 v3 = __ldcs(&zv[(size_t)sp[k + 3] * strideV + tid]);
            float4 v4 = __ldcs(&zv[(size_t)sp[k + 4] * strideV + tid]);
            float4 v5 = __ldcs(&zv[(size_t)sp[k + 5] * strideV + tid]);
            float4 v6 = __ldcs(&zv[(size_t)sp[k + 6] * strideV + tid]);
            float4 v7 = __ldcs(&zv[(size_t)sp[k + 7] * strideV + tid]);
            a.x += ((v0.x + v1.x) + (v2.x + v3.x)) + ((v4.x + v5.x) + (v6.x + v7.x));
            a.y += ((v0.y + v1.y) + (v2.y + v3.y)) + ((v4.y + v5.y) + (v6.y + v7.y));
            a.z += ((v0.z + v1.z) + (v2.z + v3.z)) + ((v4.z + v5.z) + (v6.z + v7.z));
            a.w += ((v0.w + v1.w) + (v2.w + v3.w)) + ((v4.w + v5.w) + (v6.w + v7.w));
        }
        for (; k < n; k++) {
            float4 v = __ldcs(&zv[(size_t)sp[k] * strideV + tid]);
            a.x += v.x; a.y += v.y; a.z += v.z; a.w += v.w;
        }
    }

    float* base = g_part + (((size_t)r * 100 + c) * 2 + m) * MAXD;
    ((float4*)base)[tid] = a;
}

// ---------------- reduce partials + divide + normalize + transpose ---------
// 256 threads; threads 0..191 each own one float4 column group.

__global__ void __launch_bounds__(256)
k_norm(float* __restrict__ out, const int* __restrict__ task_id) {
    int end_i = (*task_id + 1) * 10;
    int C2    = 2 * end_i;
    int i = blockIdx.x;
    if (i >= C2) return;

    int m = (i >= end_i) ? 1 : 0;
    int c = m ? (i - end_i) : i;
    int cnt = g_counts[c];
    float inv = 1.0f / (float)max(cnt, 1);
    int tid = threadIdx.x;

    float4 v = make_float4(0.f, 0.f, 0.f, 0.f);
    float ssq = 0.f;
    if (tid < 192) {
        const float4* __restrict__ p0 =
            (const float4*)(g_part + ((size_t)c * 2 + m) * MAXD) + tid;
        const size_t rstep = (size_t)100 * 2 * MAXD / 4;  // float4 stride per r
        float4 t0 = p0[0],          t1 = p0[rstep],     t2 = p0[2 * rstep], t3 = p0[3 * rstep];
        float4 t4 = p0[4 * rstep],  t5 = p0[5 * rstep], t6 = p0[6 * rstep], t7 = p0[7 * rstep];
        v.x = (((t0.x + t1.x) + (t2.x + t3.x)) + ((t4.x + t5.x) + (t6.x + t7.x))) * inv;
        v.y = (((t0.y + t1.y) + (t2.y + t3.y)) + ((t4.y + t5.y) + (t6.y + t7.y))) * inv;
        v.z = (((t0.z + t1.z) + (t2.z + t3.z)) + ((t4.z + t5.z) + (t6.z + t7.z))) * inv;
        v.w = (((t0.w + t1.w) + (t2.w + t3.w)) + ((t4.w + t5.w) + (t6.w + t7.w))) * inv;
        ssq = v.x * v.x + v.y * v.y + v.z * v.z + v.w * v.w;

        float* o = out + 1 + (size_t)i * MAXD + tid * 4;
        o[0] = v.x; o[1] = v.y; o[2] = v.z; o[3] = v.w;
    }

    __shared__ float red[256];
    red[tid] = ssq;
    __syncthreads();
    for (int s = 128; s > 0; s >>= 1) {
        if (tid < s) red[tid] += red[tid + s];
        __syncthreads();
    }
    float scale = 1.0f / fmaxf(sqrtf(red[0]), 1e-12f);

    if (tid < 192) {
        float4 zn = make_float4(v.x * scale, v.y * scale, v.z * scale, v.w * scale);
        ((float4*)(g_znorm + (size_t)i * MAXD))[tid] = zn;
        int col = tid * 4;
        g_znormT[(size_t)(col + 0) * MAXC2 + i] = zn.x;
        g_znormT[(size_t)(col + 1) * MAXC2 + i] = zn.y;
        g_znormT[(size_t)(col + 2) * MAXC2 + i] = zn.z;
        g_znormT[(size_t)(col + 3) * MAXC2 + i] = zn.w;
    }
}

// ---------------- fused logits + softmax rowloss + final -------------------
// 50 blocks x 256 threads; block b handles rows 4b..4b+3.

#define LROWS 4
__global__ void __launch_bounds__(256)
k_loss(float* __restrict__ out, const int* __restrict__ task_id) {
    int end_i = (*task_id + 1) * 10;
    int C2    = 2 * end_i;
    int i0 = blockIdx.x * LROWS;
    int tid = threadIdx.x;

    __shared__ float srow[LROWS][MAXD];
    __shared__ float red[256];
    __shared__ float sh_m, sh_s;
    __shared__ int   shcnt[MAXC];
    __shared__ bool  lastblk;

    bool act = (i0 < C2);

    for (int t = tid; t < MAXC; t += 256) shcnt[t] = g_counts[t];
    if (act) {
        for (int t = tid; t < MAXD * LROWS; t += 256) {
            int rr = t / MAXD, cc = t % MAXD;
            srow[rr][cc] = g_znorm[(size_t)(i0 + rr) * MAXD + cc];
        }
    }
    __syncthreads();

    float lrow[LROWS] = {0.f, 0.f, 0.f, 0.f};
    if (act) {
        float p[LROWS][2];
#pragma unroll
        for (int r = 0; r < LROWS; r++) { p[r][0] = 0.f; p[r][1] = 0.f; }
        const float* __restrict__ zT = g_znormT;
#pragma unroll 1
        for (int k0 = 0; k0 < MAXD; k0 += 8) {
            float vv[8];
#pragma unroll
            for (int u = 0; u < 8; u++) vv[u] = zT[(size_t)(k0 + u) * MAXC2 + tid];
#pragma unroll
            for (int u = 0; u < 8; u++)
#pragma unroll
                for (int r = 0; r < LROWS; r++)
                    p[r][u & 1] = fmaf(srow[r][k0 + u], vv[u], p[r][u & 1]);
        }
#pragma unroll
        for (int r = 0; r < LROWS; r++) lrow[r] = (p[r][0] + p[r][1]) * 2.0f;
    }

    int  cls = (tid < end_i) ? tid : tid - end_i;
    bool vj  = (tid < C2) && (shcnt[cls] > 0);

    for (int rr = 0; rr < LROWS; rr++) {
        int   i  = i0 + rr;
        float lv = lrow[rr];
        if (act) {
            red[tid] = vj ? lv : -FLT_MAX;
            __syncthreads();
            for (int s = 128; s > 0; s >>= 1) {
                if (tid < s) red[tid] = fmaxf(red[tid], red[tid + s]);
                __syncthreads();
            }
            if (tid == 0) sh_m = red[0];
            __syncthreads();
            float m = sh_m;

            red[tid] = (vj && tid != i) ? expf(lv - m) : 0.f;
            __syncthreads();
            for (int s = 128; s > 0; s >>= 1) {
                if (tid < s) red[tid] += red[tid + s];
                __syncthreads();
            }
            if (tid == 0) sh_s = red[0];
            __syncthreads();
            float S = sh_s;

            int jpos = i + end_i;
            if (jpos >= C2) jpos -= C2;
            if (tid == jpos) {
                int  icls = (i < end_i) ? i : i - end_i;
                bool vi   = shcnt[icls] > 0;
                g_rowloss[i] = (vi && vj) ? ((lv - m) - logf(S)) : 0.f;
            }
            __syncthreads();
        }
    }

    __threadfence();
    if (tid == 0)
        lastblk = (atomicAdd(&g_ctr2, 1u) == gridDim.x - 1);
    __syncthreads();
    if (lastblk) {
        __threadfence();
        float l = (tid < C2) ? g_rowloss[tid] : 0.f;
        red[tid] = l;
        __syncthreads();
        for (int s = 128; s > 0; s >>= 1) {
            if (tid < s) red[tid] += red[tid + s];
            __syncthreads();
        }
        float lsum = red[0];
        __syncthreads();
        red[tid] = vj ? 1.f : 0.f;
        __syncthreads();
        for (int s = 128; s > 0; s >>= 1) {
            if (tid < s) red[tid] += red[tid + s];
            __syncthreads();
        }
        if (tid == 0) out[0] = -lsum / fmaxf(red[0], 1.0f);
        // reset persistent state for next call
        if (tid < MAXC) g_counts[tid] = 0;
        if (tid == 0)   g_ctr2 = 0;
    }
}

// ---------------- launch ----------------------------------------------------

extern "C" void kernel_launch(void* const* d_in, const int* in_sizes, int n_in,
                              void* d_out, int out_size) {
    const float* z1      = (const float*)d_in[0];
    const float* z2      = (const float*)d_in[1];
    const int*   labels  = (const int*)d_in[2];
    const int*   task_id = (const int*)d_in[3];
    float*       out     = (float*)d_out;

    int N = in_sizes[2];

    k_hist<<<SC_BLOCKS, H_TPB>>>(labels, N, task_id);
    k_scatter<<<SC_BLOCKS, SC_TPB>>>(labels, N, task_id);

    dim3 gseg(100, RSPLIT, 2);
    k_segsum<<<gseg, SEG_TPB>>>(z1, z2, task_id);

    k_norm<<<200, 256>>>(out, task_id);
    k_loss<<<50, 256>>>(out, task_id);
}